// round 2
// baseline (speedup 1.0000x reference)
#include <cuda_runtime.h>
#include <cstdint>

#define N_NODES 100000
#define N_EDGES 600000
#define HIDDEN  128
#define ALPHA   0.1f
#define KHOPS   10

// ---------------- device scratch (static; no allocation) ----------------
__device__ float g_h0  [(size_t)N_NODES * HIDDEN];
__device__ float g_bufA[(size_t)N_NODES * HIDDEN];
__device__ float g_bufB[(size_t)N_NODES * HIDDEN];
__device__ float g_deg  [N_NODES];
__device__ float g_dinv [N_NODES];
__device__ float g_selfw[N_NODES];   // (1-alpha) * dinv^2  (self-loop weight)
__device__ int   g_src[N_EDGES];
__device__ int   g_dst[N_EDGES];
__device__ float g_nrm[N_EDGES];     // (1-alpha) * dinv[s] * dinv[d]
__device__ int   g_is64;             // 1 if edge_index is int64, 0 if int32

// ---------------- dtype probe ----------------
// If edge_index is int64 (little-endian), the high 32-bit word of every entry
// is 0 (indices are in [0, 100000)). If it is int32, those word positions hold
// random indices, which are ~never all zero across 128 samples.
__global__ void dtype_probe(const int* __restrict__ ei32) {
    if (threadIdx.x == 0 && blockIdx.x == 0) {
        int acc = 0;
        for (int i = 0; i < 128; i++) acc |= ei32[2 * i + 1];
        g_is64 = (acc == 0) ? 1 : 0;
    }
}

__device__ __forceinline__ int load_idx(const int* ei32, long long pos, int is64) {
    // pos = logical element index into a (2*N_EDGES)-element index array
    return is64 ? ei32[2 * pos] : ei32[pos];
}

// ---------------- degree / norm precompute ----------------
__global__ void deg_init(float* __restrict__ deg) {
    int i = blockIdx.x * 256 + threadIdx.x;
    if (i < N_NODES) deg[i] = 1.0f;   // self-loop
}

__global__ void deg_count(const int* __restrict__ ei32, float* __restrict__ deg) {
    int e = blockIdx.x * 256 + threadIdx.x;
    if (e < N_EDGES) {
        int is64 = g_is64;
        int d = load_idx(ei32, (long long)N_EDGES + e, is64);
        if ((unsigned)d < N_NODES) atomicAdd(&deg[d], 1.0f);
    }
}

__global__ void node_prep(const float* __restrict__ deg,
                          float* __restrict__ dinv, float* __restrict__ selfw) {
    int i = blockIdx.x * 256 + threadIdx.x;
    if (i < N_NODES) {
        float r = rsqrtf(deg[i]);     // deg >= 1 always
        dinv[i]  = r;
        selfw[i] = (1.0f - ALPHA) * r * r;
    }
}

__global__ void edge_prep(const int* __restrict__ ei32, const float* __restrict__ dinv,
                          int* __restrict__ src, int* __restrict__ dst, float* __restrict__ nrm) {
    int e = blockIdx.x * 256 + threadIdx.x;
    if (e < N_EDGES) {
        int is64 = g_is64;
        int s = load_idx(ei32, e, is64);
        int d = load_idx(ei32, (long long)N_EDGES + e, is64);
        if ((unsigned)s >= N_NODES) s = 0;
        if ((unsigned)d >= N_NODES) d = 0;
        src[e] = s;
        dst[e] = d;
        nrm[e] = (1.0f - ALPHA) * dinv[s] * dinv[d];
    }
}

// ---------------- GEMM: h0 = x @ W^T + b ----------------
// Block: 256 threads, tile = 32 rows x 128 cols, 4x4 register blocking, K chunked by 32.
__global__ __launch_bounds__(256) void gemm_kernel(
    const float* __restrict__ x, const float* __restrict__ W,
    const float* __restrict__ b, float* __restrict__ out)
{
    __shared__ __align__(16) float xs[32][36];    // xs[k][r]
    __shared__ __align__(16) float ws[32][132];   // ws[k][c]

    const int tid = threadIdx.x;
    const int rowbase = blockIdx.x * 32;
    const int tx = tid & 31;   // col group: c0 = 4*tx  (covers 128)
    const int ty = tid >> 5;   // row group: r0 = 4*ty  (covers 32)

    float acc[4][4];
#pragma unroll
    for (int i = 0; i < 4; i++)
#pragma unroll
        for (int j = 0; j < 4; j++) acc[i][j] = 0.0f;

    const int lk = tid & 31;
    const int lr = tid >> 5;   // 0..7

    for (int kc = 0; kc < HIDDEN; kc += 32) {
        // load x tile: 32 rows x 32 k (coalesced over k)
#pragma unroll
        for (int i = 0; i < 4; i++) {
            int r = lr + 8 * i;
            xs[lk][r] = x[(size_t)(rowbase + r) * HIDDEN + kc + lk];
        }
        // load W tile: 128 cols x 32 k (coalesced over k)
#pragma unroll
        for (int i = 0; i < 16; i++) {
            int c = lr + 8 * i;
            ws[lk][c] = W[(size_t)c * HIDDEN + kc + lk];
        }
        __syncthreads();

#pragma unroll
        for (int k = 0; k < 32; k++) {
            float4 wv = *(const float4*)&ws[k][tx * 4];
            float xv0 = xs[k][ty * 4 + 0];
            float xv1 = xs[k][ty * 4 + 1];
            float xv2 = xs[k][ty * 4 + 2];
            float xv3 = xs[k][ty * 4 + 3];
            acc[0][0] += xv0 * wv.x; acc[0][1] += xv0 * wv.y; acc[0][2] += xv0 * wv.z; acc[0][3] += xv0 * wv.w;
            acc[1][0] += xv1 * wv.x; acc[1][1] += xv1 * wv.y; acc[1][2] += xv1 * wv.z; acc[1][3] += xv1 * wv.w;
            acc[2][0] += xv2 * wv.x; acc[2][1] += xv2 * wv.y; acc[2][2] += xv2 * wv.z; acc[2][3] += xv2 * wv.w;
            acc[3][0] += xv3 * wv.x; acc[3][1] += xv3 * wv.y; acc[3][2] += xv3 * wv.z; acc[3][3] += xv3 * wv.w;
        }
        __syncthreads();
    }

    float4 bias = *(const float4*)&b[tx * 4];
#pragma unroll
    for (int i = 0; i < 4; i++) {
        float4 o;
        o.x = acc[i][0] + bias.x;
        o.y = acc[i][1] + bias.y;
        o.z = acc[i][2] + bias.z;
        o.w = acc[i][3] + bias.w;
        *(float4*)&out[(size_t)(rowbase + ty * 4 + i) * HIDDEN + tx * 4] = o;
    }
}

// ---------------- per-hop: init out = alpha*h0 + selfw*h ----------------
__global__ __launch_bounds__(256) void hop_init(
    const float* __restrict__ h, const float* __restrict__ h0,
    const float* __restrict__ selfw, float* __restrict__ out)
{
    size_t i = (size_t)blockIdx.x * 256 + threadIdx.x;  // over N*H/4 float4 elems
    int node = (int)(i >> 5);                            // 32 float4 per node
    float sw = selfw[node];
    float4 hv  = ((const float4*)h)[i];
    float4 h0v = ((const float4*)h0)[i];
    float4 o;
    o.x = ALPHA * h0v.x + sw * hv.x;
    o.y = ALPHA * h0v.y + sw * hv.y;
    o.z = ALPHA * h0v.z + sw * hv.z;
    o.w = ALPHA * h0v.w + sw * hv.w;
    ((float4*)out)[i] = o;
}

// ---------------- per-hop: scatter edge messages (warp per edge) ----------------
__global__ __launch_bounds__(256) void edge_msg(
    const float* __restrict__ h,
    const int* __restrict__ src, const int* __restrict__ dst,
    const float* __restrict__ nrm, float* __restrict__ out)
{
    int gtid = blockIdx.x * 256 + threadIdx.x;
    int e = gtid >> 5;
    int lane = gtid & 31;
    if (e >= N_EDGES) return;
    int s = src[e];
    int d = dst[e];
    float w = nrm[e];
    float4 v = *(const float4*)(h + (size_t)s * HIDDEN + lane * 4);
    v.x *= w; v.y *= w; v.z *= w; v.w *= w;
    float* p = out + (size_t)d * HIDDEN + lane * 4;
    asm volatile("red.global.add.v4.f32 [%0], {%1, %2, %3, %4};"
                 :: "l"(p), "f"(v.x), "f"(v.y), "f"(v.z), "f"(v.w) : "memory");
}

// ---------------- launch ----------------
extern "C" void kernel_launch(void* const* d_in, const int* in_sizes, int n_in,
                              void* d_out, int out_size)
{
    const float* x    = (const float*)d_in[0];
    const int*   ei32 = (const int*)d_in[1];    // int32 OR int64 (probed on device)
    const float* W    = (const float*)d_in[2];
    const float* b    = (const float*)d_in[3];
    float* out = (float*)d_out;

    float *h0, *bufA, *bufB, *deg, *dinv, *selfw, *nrm;
    int *src, *dst;
    cudaGetSymbolAddress((void**)&h0,    g_h0);
    cudaGetSymbolAddress((void**)&bufA,  g_bufA);
    cudaGetSymbolAddress((void**)&bufB,  g_bufB);
    cudaGetSymbolAddress((void**)&deg,   g_deg);
    cudaGetSymbolAddress((void**)&dinv,  g_dinv);
    cudaGetSymbolAddress((void**)&selfw, g_selfw);
    cudaGetSymbolAddress((void**)&src,   g_src);
    cudaGetSymbolAddress((void**)&dst,   g_dst);
    cudaGetSymbolAddress((void**)&nrm,   g_nrm);

    const int NB_N = (N_NODES + 255) / 256;   // 391
    const int NB_E = (N_EDGES + 255) / 256;   // 2344

    dtype_probe<<<1, 32>>>(ei32);
    deg_init <<<NB_N, 256>>>(deg);
    deg_count<<<NB_E, 256>>>(ei32, deg);
    node_prep<<<NB_N, 256>>>(deg, dinv, selfw);
    edge_prep<<<NB_E, 256>>>(ei32, dinv, src, dst, nrm);

    gemm_kernel<<<N_NODES / 32, 256>>>(x, W, b, h0);   // 3125 blocks

    const int NB_INIT = (N_NODES * HIDDEN / 4) / 256;  // 12500
    const int NB_MSG  = (N_EDGES * 32) / 256;          // 75000

    const float* cur = h0;
    for (int hop = 0; hop < KHOPS; hop++) {
        float* nxt = (hop == KHOPS - 1) ? out : ((hop & 1) ? bufB : bufA);
        hop_init<<<NB_INIT, 256>>>(cur, h0, selfw, nxt);
        edge_msg<<<NB_MSG, 256>>>(cur, src, dst, nrm, nxt);
        cur = nxt;
    }
}

// round 3
// speedup vs baseline: 1.5846x; 1.5846x over previous
#include <cuda_runtime.h>
#include <cstdint>

#define N_NODES 100000
#define N_EDGES 600000
#define HIDDEN  128
#define ALPHA   0.1f
#define KHOPS   10

// ---------------- device scratch (static; no allocation) ----------------
__device__ float g_h0  [(size_t)N_NODES * HIDDEN];
__device__ float g_bufA[(size_t)N_NODES * HIDDEN];
__device__ float g_bufB[(size_t)N_NODES * HIDDEN];
__device__ int   g_cnt    [N_NODES];
__device__ int   g_rowptr [N_NODES + 1];
__device__ int   g_cursor [N_NODES];
__device__ float g_dinv   [N_NODES];
__device__ float g_selfw  [N_NODES];   // (1-alpha) * dinv^2
__device__ int   g_csrc   [N_EDGES];   // CSR (by dst): source node per slot
__device__ float g_cw     [N_EDGES];   // CSR edge weight (1-alpha)*dinv[s]*dinv[d]
__device__ int   g_is64;               // 1 if edge_index is int64, 0 if int32

// ---------------- dtype probe ----------------
// int64 little-endian: high word of every entry is 0 (indices < 100000).
// int32: those positions hold random indices -> never all zero over 128 samples.
__global__ void dtype_probe(const int* __restrict__ ei32) {
    if (threadIdx.x == 0) {
        int acc = 0;
        for (int i = 0; i < 128; i++) acc |= ei32[2 * i + 1];
        g_is64 = (acc == 0) ? 1 : 0;
    }
}

__device__ __forceinline__ int load_idx(const int* ei32, long long pos, int is64) {
    return is64 ? ei32[2 * pos] : ei32[pos];
}

// ---------------- CSR build ----------------
__global__ void cnt_zero(int* __restrict__ cnt) {
    int i = blockIdx.x * 256 + threadIdx.x;
    if (i < N_NODES) cnt[i] = 0;
}

__global__ void deg_count(const int* __restrict__ ei32, int* __restrict__ cnt) {
    int e = blockIdx.x * 256 + threadIdx.x;
    if (e < N_EDGES) {
        int d = load_idx(ei32, (long long)N_EDGES + e, g_is64);
        if ((unsigned)d < N_NODES) atomicAdd(&cnt[d], 1);
    }
}

__global__ void node_prep(const int* __restrict__ cnt,
                          float* __restrict__ dinv, float* __restrict__ selfw) {
    int i = blockIdx.x * 256 + threadIdx.x;
    if (i < N_NODES) {
        float r = rsqrtf((float)cnt[i] + 1.0f);   // +1 self-loop
        dinv[i]  = r;
        selfw[i] = (1.0f - ALPHA) * r * r;
    }
}

// single-block exclusive scan: each thread serially sums a chunk, block-scans
// the 1024 chunk totals, then serially writes row_ptr + cursor.
__global__ __launch_bounds__(1024) void scan_kernel(
    const int* __restrict__ cnt, int* __restrict__ row_ptr, int* __restrict__ cursor)
{
    const int PER = (N_NODES + 1023) / 1024;   // 98
    int t = threadIdx.x;
    int start = t * PER;
    int local = 0;
    for (int k = 0; k < PER; k++) {
        int i = start + k;
        if (i < N_NODES) local += cnt[i];
    }
    __shared__ int sh[1024];
    sh[t] = local;
    __syncthreads();
    for (int d = 1; d < 1024; d <<= 1) {
        int v = (t >= d) ? sh[t - d] : 0;
        __syncthreads();
        sh[t] += v;
        __syncthreads();
    }
    int run = sh[t] - local;   // exclusive prefix of this chunk
    for (int k = 0; k < PER; k++) {
        int i = start + k;
        if (i < N_NODES) {
            row_ptr[i] = run;
            cursor[i]  = run;
            run += cnt[i];
        }
    }
    if (t == 1023) row_ptr[N_NODES] = sh[1023];
}

__global__ void edge_place(const int* __restrict__ ei32, const float* __restrict__ dinv,
                           int* __restrict__ cursor,
                           int* __restrict__ csrc, float* __restrict__ cw)
{
    int e = blockIdx.x * 256 + threadIdx.x;
    if (e < N_EDGES) {
        int is64 = g_is64;
        int s = load_idx(ei32, e, is64);
        int d = load_idx(ei32, (long long)N_EDGES + e, is64);
        if ((unsigned)s >= N_NODES) s = 0;
        if ((unsigned)d >= N_NODES) d = 0;
        int pos = atomicAdd(&cursor[d], 1);
        csrc[pos] = s;
        cw[pos]   = (1.0f - ALPHA) * dinv[s] * dinv[d];
    }
}

// ---------------- GEMM: h0 = x @ W^T + b ----------------
__global__ __launch_bounds__(256) void gemm_kernel(
    const float* __restrict__ x, const float* __restrict__ W,
    const float* __restrict__ b, float* __restrict__ out)
{
    __shared__ __align__(16) float xs[32][36];    // xs[k][r]
    __shared__ __align__(16) float ws[32][132];   // ws[k][c]

    const int tid = threadIdx.x;
    const int rowbase = blockIdx.x * 32;
    const int tx = tid & 31;   // col group: c0 = 4*tx
    const int ty = tid >> 5;   // row group: r0 = 4*ty

    float acc[4][4];
#pragma unroll
    for (int i = 0; i < 4; i++)
#pragma unroll
        for (int j = 0; j < 4; j++) acc[i][j] = 0.0f;

    const int lk = tid & 31;
    const int lr = tid >> 5;

    for (int kc = 0; kc < HIDDEN; kc += 32) {
#pragma unroll
        for (int i = 0; i < 4; i++) {
            int r = lr + 8 * i;
            xs[lk][r] = x[(size_t)(rowbase + r) * HIDDEN + kc + lk];
        }
#pragma unroll
        for (int i = 0; i < 16; i++) {
            int c = lr + 8 * i;
            ws[lk][c] = W[(size_t)c * HIDDEN + kc + lk];
        }
        __syncthreads();

#pragma unroll
        for (int k = 0; k < 32; k++) {
            float4 wv = *(const float4*)&ws[k][tx * 4];
            float xv0 = xs[k][ty * 4 + 0];
            float xv1 = xs[k][ty * 4 + 1];
            float xv2 = xs[k][ty * 4 + 2];
            float xv3 = xs[k][ty * 4 + 3];
            acc[0][0] += xv0 * wv.x; acc[0][1] += xv0 * wv.y; acc[0][2] += xv0 * wv.z; acc[0][3] += xv0 * wv.w;
            acc[1][0] += xv1 * wv.x; acc[1][1] += xv1 * wv.y; acc[1][2] += xv1 * wv.z; acc[1][3] += xv1 * wv.w;
            acc[2][0] += xv2 * wv.x; acc[2][1] += xv2 * wv.y; acc[2][2] += xv2 * wv.z; acc[2][3] += xv2 * wv.w;
            acc[3][0] += xv3 * wv.x; acc[3][1] += xv3 * wv.y; acc[3][2] += xv3 * wv.z; acc[3][3] += xv3 * wv.w;
        }
        __syncthreads();
    }

    float4 bias = *(const float4*)&b[tx * 4];
#pragma unroll
    for (int i = 0; i < 4; i++) {
        float4 o;
        o.x = acc[i][0] + bias.x;
        o.y = acc[i][1] + bias.y;
        o.z = acc[i][2] + bias.z;
        o.w = acc[i][3] + bias.w;
        *(float4*)&out[(size_t)(rowbase + ty * 4 + i) * HIDDEN + tx * 4] = o;
    }
}

// ---------------- per-hop fused pull kernel: warp per node ----------------
// out[n] = alpha*h0[n] + selfw[n]*cur[n] + sum_e w_e * cur[src_e]
__global__ __launch_bounds__(256) void prop_kernel(
    const float* __restrict__ cur, const float* __restrict__ h0,
    const float* __restrict__ selfw,
    const int* __restrict__ row_ptr, const int* __restrict__ csrc,
    const float* __restrict__ cw, float* __restrict__ out)
{
    int gtid = blockIdx.x * 256 + threadIdx.x;
    int n = gtid >> 5;
    int lane = gtid & 31;
    if (n >= N_NODES) return;

    const float4* curv = (const float4*)cur;
    size_t ridx = (size_t)n * 32 + lane;

    float4 h0v = ((const float4*)h0)[ridx];
    float4 sv  = curv[ridx];
    float sw = selfw[n];
    float4 acc;
    acc.x = ALPHA * h0v.x + sw * sv.x;
    acc.y = ALPHA * h0v.y + sw * sv.y;
    acc.z = ALPHA * h0v.z + sw * sv.z;
    acc.w = ALPHA * h0v.w + sw * sv.w;

    int beg = row_ptr[n];
    int end = row_ptr[n + 1];
    int j = beg;
    // 4-way unrolled gather for MLP
    for (; j + 4 <= end; j += 4) {
        int   s0 = csrc[j],   s1 = csrc[j+1],   s2 = csrc[j+2],   s3 = csrc[j+3];
        float w0 = cw[j],     w1 = cw[j+1],     w2 = cw[j+2],     w3 = cw[j+3];
        float4 v0 = curv[(size_t)s0 * 32 + lane];
        float4 v1 = curv[(size_t)s1 * 32 + lane];
        float4 v2 = curv[(size_t)s2 * 32 + lane];
        float4 v3 = curv[(size_t)s3 * 32 + lane];
        acc.x += w0*v0.x + w1*v1.x + w2*v2.x + w3*v3.x;
        acc.y += w0*v0.y + w1*v1.y + w2*v2.y + w3*v3.y;
        acc.z += w0*v0.z + w1*v1.z + w2*v2.z + w3*v3.z;
        acc.w += w0*v0.w + w1*v1.w + w2*v2.w + w3*v3.w;
    }
    for (; j < end; j++) {
        int s = csrc[j];
        float w = cw[j];
        float4 v = curv[(size_t)s * 32 + lane];
        acc.x += w * v.x;
        acc.y += w * v.y;
        acc.z += w * v.z;
        acc.w += w * v.w;
    }

    ((float4*)out)[ridx] = acc;
}

// ---------------- launch ----------------
extern "C" void kernel_launch(void* const* d_in, const int* in_sizes, int n_in,
                              void* d_out, int out_size)
{
    const float* x    = (const float*)d_in[0];
    const int*   ei32 = (const int*)d_in[1];    // int32 OR int64 (device probe)
    const float* W    = (const float*)d_in[2];
    const float* b    = (const float*)d_in[3];
    float* out = (float*)d_out;

    float *h0, *bufA, *bufB, *dinv, *selfw, *cw;
    int *cnt, *row_ptr, *cursor, *csrc;
    cudaGetSymbolAddress((void**)&h0,      g_h0);
    cudaGetSymbolAddress((void**)&bufA,    g_bufA);
    cudaGetSymbolAddress((void**)&bufB,    g_bufB);
    cudaGetSymbolAddress((void**)&cnt,     g_cnt);
    cudaGetSymbolAddress((void**)&row_ptr, g_rowptr);
    cudaGetSymbolAddress((void**)&cursor,  g_cursor);
    cudaGetSymbolAddress((void**)&dinv,    g_dinv);
    cudaGetSymbolAddress((void**)&selfw,   g_selfw);
    cudaGetSymbolAddress((void**)&csrc,    g_csrc);
    cudaGetSymbolAddress((void**)&cw,      g_cw);

    const int NB_N = (N_NODES + 255) / 256;   // 391
    const int NB_E = (N_EDGES + 255) / 256;   // 2344

    dtype_probe<<<1, 32>>>(ei32);
    cnt_zero   <<<NB_N, 256>>>(cnt);
    deg_count  <<<NB_E, 256>>>(ei32, cnt);
    node_prep  <<<NB_N, 256>>>(cnt, dinv, selfw);
    scan_kernel<<<1, 1024>>>(cnt, row_ptr, cursor);
    edge_place <<<NB_E, 256>>>(ei32, dinv, cursor, csrc, cw);

    gemm_kernel<<<N_NODES / 32, 256>>>(x, W, b, h0);

    const int NB_PROP = (N_NODES * 32 + 255) / 256;  // 12500
    const float* cur = h0;
    for (int hop = 0; hop < KHOPS; hop++) {
        float* nxt = (hop == KHOPS - 1) ? out : ((hop & 1) ? bufB : bufA);
        prop_kernel<<<NB_PROP, 256>>>(cur, h0, selfw, row_ptr, csrc, cw, nxt);
        cur = nxt;
    }
}

// round 4
// speedup vs baseline: 1.6946x; 1.0694x over previous
#include <cuda_runtime.h>
#include <cuda_fp16.h>
#include <cstdint>

#define N_NODES 100000
#define N_EDGES 600000
#define HIDDEN  128
#define ALPHA   0.1f
#define KHOPS   10

// ---------------- device scratch (static; no allocation) ----------------
__device__ __half g_h0h [(size_t)N_NODES * HIDDEN];
__device__ __half g_bufA[(size_t)N_NODES * HIDDEN];
__device__ __half g_bufB[(size_t)N_NODES * HIDDEN];
__device__ int    g_cnt    [N_NODES];
__device__ int    g_rowptr [N_NODES + 1];
__device__ int    g_cursor [N_NODES];
__device__ float  g_dinv   [N_NODES];
__device__ float  g_selfw  [N_NODES];   // (1-alpha) * dinv^2
__device__ int2   g_edge   [N_EDGES];   // CSR by dst: {src, weight-as-int-bits}
__device__ int    g_is64;               // 1 if edge_index is int64, 0 if int32

// ---------------- fp16 vector helpers ----------------
__device__ __forceinline__ float4 ldh4(const __half* p) {
    uint2 raw = *(const uint2*)p;
    __half2 a = *(__half2*)&raw.x;
    __half2 b = *(__half2*)&raw.y;
    float2 fa = __half22float2(a);
    float2 fb = __half22float2(b);
    return make_float4(fa.x, fa.y, fb.x, fb.y);
}
__device__ __forceinline__ void sth4(__half* p, float4 v) {
    __half2 a = __floats2half2_rn(v.x, v.y);
    __half2 b = __floats2half2_rn(v.z, v.w);
    uint2 raw;
    raw.x = *(unsigned*)&a;
    raw.y = *(unsigned*)&b;
    *(uint2*)p = raw;
}

// ---------------- launch 0: dtype probe + zero counts ----------------
// int64 little-endian: high word of every entry is 0 (indices < 100000).
// int32: those positions hold random indices -> never all zero over 128 samples.
__global__ void probe_zero(const int* __restrict__ ei32, int* __restrict__ cnt) {
    int i = blockIdx.x * 256 + threadIdx.x;
    if (i < N_NODES) cnt[i] = 0;
    if (i == 0) {
        int acc = 0;
        for (int k = 0; k < 128; k++) acc |= ei32[2 * k + 1];
        g_is64 = (acc == 0) ? 1 : 0;
    }
}

__device__ __forceinline__ int load_idx(const int* ei32, long long pos, int is64) {
    return is64 ? ei32[2 * pos] : ei32[pos];
}

// ---------------- launch 1: in-degree count ----------------
__global__ void deg_count(const int* __restrict__ ei32, int* __restrict__ cnt) {
    int e = blockIdx.x * 256 + threadIdx.x;
    if (e < N_EDGES) {
        int d = load_idx(ei32, (long long)N_EDGES + e, g_is64);
        if ((unsigned)d < N_NODES) atomicAdd(&cnt[d], 1);
    }
}

// ---------------- launch 2: exclusive scan + node norm prep (fused) ----------------
__global__ __launch_bounds__(1024) void scan_prep(
    const int* __restrict__ cnt, int* __restrict__ row_ptr, int* __restrict__ cursor,
    float* __restrict__ dinv, float* __restrict__ selfw)
{
    const int PER = (N_NODES + 1023) / 1024;   // 98
    int t = threadIdx.x;
    int start = t * PER;
    int local = 0;
    for (int k = 0; k < PER; k++) {
        int i = start + k;
        if (i < N_NODES) local += cnt[i];
    }
    __shared__ int sh[1024];
    sh[t] = local;
    __syncthreads();
    for (int d = 1; d < 1024; d <<= 1) {
        int v = (t >= d) ? sh[t - d] : 0;
        __syncthreads();
        sh[t] += v;
        __syncthreads();
    }
    int run = sh[t] - local;   // exclusive prefix of this chunk
    for (int k = 0; k < PER; k++) {
        int i = start + k;
        if (i < N_NODES) {
            row_ptr[i] = run;
            cursor[i]  = run;
            run += cnt[i];
            float r = rsqrtf((float)cnt[i] + 1.0f);   // +1 self-loop
            dinv[i]  = r;
            selfw[i] = (1.0f - ALPHA) * r * r;
        }
    }
    if (t == 1023) row_ptr[N_NODES] = sh[1023];
}

// ---------------- launch 3: GEMM h0 = x @ W^T + b (fp16 out) ----------------
__global__ __launch_bounds__(256) void gemm_kernel(
    const float* __restrict__ x, const float* __restrict__ W,
    const float* __restrict__ b, __half* __restrict__ out)
{
    __shared__ __align__(16) float xs[32][36];    // xs[k][r]
    __shared__ __align__(16) float ws[32][132];   // ws[k][c]

    const int tid = threadIdx.x;
    const int rowbase = blockIdx.x * 32;
    const int tx = tid & 31;   // col group: c0 = 4*tx
    const int ty = tid >> 5;   // row group: r0 = 4*ty

    float acc[4][4];
#pragma unroll
    for (int i = 0; i < 4; i++)
#pragma unroll
        for (int j = 0; j < 4; j++) acc[i][j] = 0.0f;

    const int lk = tid & 31;
    const int lr = tid >> 5;

    for (int kc = 0; kc < HIDDEN; kc += 32) {
#pragma unroll
        for (int i = 0; i < 4; i++) {
            int r = lr + 8 * i;
            xs[lk][r] = x[(size_t)(rowbase + r) * HIDDEN + kc + lk];
        }
#pragma unroll
        for (int i = 0; i < 16; i++) {
            int c = lr + 8 * i;
            ws[lk][c] = W[(size_t)c * HIDDEN + kc + lk];
        }
        __syncthreads();

#pragma unroll
        for (int k = 0; k < 32; k++) {
            float4 wv = *(const float4*)&ws[k][tx * 4];
            float xv0 = xs[k][ty * 4 + 0];
            float xv1 = xs[k][ty * 4 + 1];
            float xv2 = xs[k][ty * 4 + 2];
            float xv3 = xs[k][ty * 4 + 3];
            acc[0][0] += xv0 * wv.x; acc[0][1] += xv0 * wv.y; acc[0][2] += xv0 * wv.z; acc[0][3] += xv0 * wv.w;
            acc[1][0] += xv1 * wv.x; acc[1][1] += xv1 * wv.y; acc[1][2] += xv1 * wv.z; acc[1][3] += xv1 * wv.w;
            acc[2][0] += xv2 * wv.x; acc[2][1] += xv2 * wv.y; acc[2][2] += xv2 * wv.z; acc[2][3] += xv2 * wv.w;
            acc[3][0] += xv3 * wv.x; acc[3][1] += xv3 * wv.y; acc[3][2] += xv3 * wv.z; acc[3][3] += xv3 * wv.w;
        }
        __syncthreads();
    }

    float4 bias = *(const float4*)&b[tx * 4];
#pragma unroll
    for (int i = 0; i < 4; i++) {
        float4 o;
        o.x = acc[i][0] + bias.x;
        o.y = acc[i][1] + bias.y;
        o.z = acc[i][2] + bias.z;
        o.w = acc[i][3] + bias.w;
        sth4(&out[(size_t)(rowbase + ty * 4 + i) * HIDDEN + tx * 4], o);
    }
}

// ---------------- launch 4: CSR edge placement (packed int2) ----------------
__global__ void edge_place(const int* __restrict__ ei32, const float* __restrict__ dinv,
                           int* __restrict__ cursor, int2* __restrict__ edge)
{
    int e = blockIdx.x * 256 + threadIdx.x;
    if (e < N_EDGES) {
        int is64 = g_is64;
        int s = load_idx(ei32, e, is64);
        int d = load_idx(ei32, (long long)N_EDGES + e, is64);
        if ((unsigned)s >= N_NODES) s = 0;
        if ((unsigned)d >= N_NODES) d = 0;
        int pos = atomicAdd(&cursor[d], 1);
        float w = (1.0f - ALPHA) * dinv[s] * dinv[d];
        edge[pos] = make_int2(s, __float_as_int(w));
    }
}

// ---------------- per-hop fused pull: warp per node, fp16 in / fp32 acc ----------------
// out[n] = alpha*h0[n] + selfw[n]*cur[n] + sum_e w_e * cur[src_e]
template <bool FINAL>
__global__ __launch_bounds__(256) void prop_kernel(
    const __half* __restrict__ cur, const __half* __restrict__ h0,
    const float* __restrict__ selfw,
    const int* __restrict__ row_ptr, const int2* __restrict__ edge,
    void* __restrict__ outp)
{
    int gtid = blockIdx.x * 256 + threadIdx.x;
    int n = gtid >> 5;
    int lane = gtid & 31;
    if (n >= N_NODES) return;

    const size_t off = (size_t)n * HIDDEN + lane * 4;
    float4 h0v = ldh4(h0 + off);
    float4 sv  = ldh4(cur + off);
    float sw = selfw[n];
    float4 acc;
    acc.x = ALPHA * h0v.x + sw * sv.x;
    acc.y = ALPHA * h0v.y + sw * sv.y;
    acc.z = ALPHA * h0v.z + sw * sv.z;
    acc.w = ALPHA * h0v.w + sw * sv.w;

    int beg = row_ptr[n];
    int end = row_ptr[n + 1];
    int j = beg;
    for (; j + 4 <= end; j += 4) {
        int2 e0 = edge[j], e1 = edge[j+1], e2 = edge[j+2], e3 = edge[j+3];
        float4 v0 = ldh4(cur + (size_t)e0.x * HIDDEN + lane * 4);
        float4 v1 = ldh4(cur + (size_t)e1.x * HIDDEN + lane * 4);
        float4 v2 = ldh4(cur + (size_t)e2.x * HIDDEN + lane * 4);
        float4 v3 = ldh4(cur + (size_t)e3.x * HIDDEN + lane * 4);
        float w0 = __int_as_float(e0.y), w1 = __int_as_float(e1.y);
        float w2 = __int_as_float(e2.y), w3 = __int_as_float(e3.y);
        acc.x += w0*v0.x + w1*v1.x + w2*v2.x + w3*v3.x;
        acc.y += w0*v0.y + w1*v1.y + w2*v2.y + w3*v3.y;
        acc.z += w0*v0.z + w1*v1.z + w2*v2.z + w3*v3.z;
        acc.w += w0*v0.w + w1*v1.w + w2*v2.w + w3*v3.w;
    }
    for (; j < end; j++) {
        int2 e = edge[j];
        float w = __int_as_float(e.y);
        float4 v = ldh4(cur + (size_t)e.x * HIDDEN + lane * 4);
        acc.x += w * v.x;
        acc.y += w * v.y;
        acc.z += w * v.z;
        acc.w += w * v.w;
    }

    if (FINAL) {
        ((float4*)outp)[(size_t)n * 32 + lane] = acc;
    } else {
        sth4((__half*)outp + off, acc);
    }
}

// ---------------- launch ----------------
extern "C" void kernel_launch(void* const* d_in, const int* in_sizes, int n_in,
                              void* d_out, int out_size)
{
    const float* x    = (const float*)d_in[0];
    const int*   ei32 = (const int*)d_in[1];    // int32 OR int64 (device probe)
    const float* W    = (const float*)d_in[2];
    const float* b    = (const float*)d_in[3];
    float* out = (float*)d_out;

    __half *h0h, *bufA, *bufB;
    float *dinv, *selfw;
    int *cnt, *row_ptr, *cursor;
    int2 *edge;
    cudaGetSymbolAddress((void**)&h0h,     g_h0h);
    cudaGetSymbolAddress((void**)&bufA,    g_bufA);
    cudaGetSymbolAddress((void**)&bufB,    g_bufB);
    cudaGetSymbolAddress((void**)&cnt,     g_cnt);
    cudaGetSymbolAddress((void**)&row_ptr, g_rowptr);
    cudaGetSymbolAddress((void**)&cursor,  g_cursor);
    cudaGetSymbolAddress((void**)&dinv,    g_dinv);
    cudaGetSymbolAddress((void**)&selfw,   g_selfw);
    cudaGetSymbolAddress((void**)&edge,    g_edge);

    const int NB_N = (N_NODES + 255) / 256;   // 391
    const int NB_E = (N_EDGES + 255) / 256;   // 2344

    probe_zero <<<NB_N, 256>>>(ei32, cnt);                       // idx 0
    deg_count  <<<NB_E, 256>>>(ei32, cnt);                       // idx 1
    scan_prep  <<<1, 1024>>>(cnt, row_ptr, cursor, dinv, selfw); // idx 2
    gemm_kernel<<<N_NODES / 32, 256>>>(x, W, b, h0h);            // idx 3 (profiled)
    edge_place <<<NB_E, 256>>>(ei32, dinv, cursor, edge);        // idx 4

    const int NB_PROP = (N_NODES * 32 + 255) / 256;  // 12500
    const __half* cur = h0h;
    for (int hop = 0; hop < KHOPS; hop++) {
        if (hop == KHOPS - 1) {
            prop_kernel<true><<<NB_PROP, 256>>>(cur, h0h, selfw, row_ptr, edge, out);
        } else {
            __half* nxt = (hop & 1) ? bufB : bufA;
            prop_kernel<false><<<NB_PROP, 256>>>(cur, h0h, selfw, row_ptr, edge, nxt);
            cur = nxt;
        }
    }
}

// round 5
// speedup vs baseline: 1.9866x; 1.1723x over previous
#include <cuda_runtime.h>
#include <cuda_fp16.h>
#include <cstdint>

#define N_NODES 100000
#define N_EDGES 600000
#define HIDDEN  128
#define ALPHA   0.1f
#define KHOPS   10
#define EDGE_CAP 1000000   // 600k edges + <=3 pad per node

// ---------------- device scratch (static; no allocation) ----------------
__device__ __half g_xh  [(size_t)N_NODES * HIDDEN];   // fp16 x
__device__ __half g_Wh  [HIDDEN * HIDDEN];            // fp16 W
__device__ __half g_h0h [(size_t)N_NODES * HIDDEN];
__device__ __half g_bufA[(size_t)N_NODES * HIDDEN];
__device__ __half g_bufB[(size_t)N_NODES * HIDDEN];
__device__ int    g_cnt    [N_NODES];
__device__ int    g_rowptr [N_NODES + 1];
__device__ int    g_cursor [N_NODES];
__device__ float  g_dinv   [N_NODES];
__device__ float  g_selfw  [N_NODES];   // (1-alpha) * dinv^2
__device__ int2   g_edge   [EDGE_CAP];  // CSR by dst: {src, weight bits}; pads are {0,0}
__device__ int    g_is64;               // 1 if edge_index is int64, 0 if int32

// ---------------- fp16 vector helpers ----------------
__device__ __forceinline__ void sth4(__half* p, float4 v) {
    __half2 a = __floats2half2_rn(v.x, v.y);
    __half2 b = __floats2half2_rn(v.z, v.w);
    uint2 raw;
    raw.x = *(unsigned*)&a;
    raw.y = *(unsigned*)&b;
    *(uint2*)p = raw;
}
// load 8 halfs -> two float4
__device__ __forceinline__ void ldh8(const __half* p, float4& lo, float4& hi) {
    uint4 raw = *(const uint4*)p;
    float2 f0 = __half22float2(*(__half2*)&raw.x);
    float2 f1 = __half22float2(*(__half2*)&raw.y);
    float2 f2 = __half22float2(*(__half2*)&raw.z);
    float2 f3 = __half22float2(*(__half2*)&raw.w);
    lo = make_float4(f0.x, f0.y, f1.x, f1.y);
    hi = make_float4(f2.x, f2.y, f3.x, f3.y);
}
__device__ __forceinline__ void fma8(float4& aL, float4& aH, float w, float4 vL, float4 vH) {
    aL.x += w * vL.x; aL.y += w * vL.y; aL.z += w * vL.z; aL.w += w * vL.w;
    aH.x += w * vH.x; aH.y += w * vH.y; aH.z += w * vH.z; aH.w += w * vH.w;
}

// ---------------- launch 0: zero counts + zero edge slab + dtype probe ----------------
__global__ void probe_zero(const int* __restrict__ ei32, int* __restrict__ cnt,
                           int2* __restrict__ edge) {
    int i = blockIdx.x * 256 + threadIdx.x;   // 100,096 threads
    if (i < N_NODES) cnt[i] = 0;
    for (int j = i; j < EDGE_CAP; j += 391 * 256) edge[j] = make_int2(0, 0);
    if (i == 0) {
        int acc = 0;
        for (int k = 0; k < 128; k++) acc |= ei32[2 * k + 1];
        g_is64 = (acc == 0) ? 1 : 0;
    }
}

__device__ __forceinline__ int load_idx(const int* ei32, long long pos, int is64) {
    return is64 ? ei32[2 * pos] : ei32[pos];
}

// ---------------- launch 1: fp32 -> fp16 conversion of x and W ----------------
__global__ __launch_bounds__(256) void convert_kernel(
    const float* __restrict__ x, const float* __restrict__ W,
    __half* __restrict__ xh, __half* __restrict__ Wh)
{
    int i = blockIdx.x * 256 + threadIdx.x;   // float4 index
    const int NX = N_NODES * HIDDEN / 4;      // 3,200,000
    if (i < NX) {
        float4 v = ((const float4*)x)[i];
        sth4(xh + (size_t)i * 4, v);
    }
    if (i < HIDDEN * HIDDEN / 4) {
        float4 v = ((const float4*)W)[i];
        sth4(Wh + (size_t)i * 4, v);
    }
}

// ---------------- launch 2: in-degree count ----------------
__global__ void deg_count(const int* __restrict__ ei32, int* __restrict__ cnt) {
    int e = blockIdx.x * 256 + threadIdx.x;
    if (e < N_EDGES) {
        int d = load_idx(ei32, (long long)N_EDGES + e, g_is64);
        if ((unsigned)d < N_NODES) atomicAdd(&cnt[d], 1);
    }
}

// ---------------- launch 3: tensor-core GEMM h0 = x @ W^T + b (fp16 in/out, fp32 acc) ----------------
#define WSTRIDE 136
__global__ __launch_bounds__(256) void gemm_hmma(
    const __half* __restrict__ xh, const __half* __restrict__ Wh,
    const float* __restrict__ b, __half* __restrict__ out)
{
    __shared__ __half Ws[128 * WSTRIDE];
    __shared__ float bs[128];
    const int tid = threadIdx.x;

    // stage all of W (128x128 fp16) into smem, padded rows (conflict-free B frags)
#pragma unroll
    for (int it = 0; it < 8; it++) {
        int idx = it * 256 + tid;            // uint4 index over [128 rows][16 uint4]
        int r = idx >> 4, c = (idx & 15) * 8;
        *(uint4*)&Ws[r * WSTRIDE + c] = ((const uint4*)Wh)[idx];
    }
    if (tid < 128) bs[tid] = b[tid];
    __syncthreads();

    const int w = tid >> 5, lane = tid & 31;
    const int r  = lane >> 2;        // 0..7
    const int kq = (lane & 3) * 2;   // 0,2,4,6
    const int Rbase = blockIdx.x * 128 + w * 16;

    int row0 = Rbase + r;
    int row1 = Rbase + r + 8;
    int row0c = row0 < N_NODES ? row0 : 0;   // clamp for loads
    int row1c = row1 < N_NODES ? row1 : 0;

    float d[16][4];
#pragma unroll
    for (int nt = 0; nt < 16; nt++)
#pragma unroll
        for (int q = 0; q < 4; q++) d[nt][q] = 0.0f;

    const __half* a0p = xh + (size_t)row0c * HIDDEN;
    const __half* a1p = xh + (size_t)row1c * HIDDEN;

#pragma unroll
    for (int ks = 0; ks < 8; ks++) {
        int k0 = ks * 16 + kq;
        unsigned a0 = *(const unsigned*)(a0p + k0);
        unsigned a1 = *(const unsigned*)(a1p + k0);
        unsigned a2 = *(const unsigned*)(a0p + k0 + 8);
        unsigned a3 = *(const unsigned*)(a1p + k0 + 8);
#pragma unroll
        for (int nt = 0; nt < 16; nt++) {
            int c = nt * 8 + r;   // B-frag col = lane>>2
            unsigned b0 = *(const unsigned*)&Ws[c * WSTRIDE + ks * 16 + kq];
            unsigned b1 = *(const unsigned*)&Ws[c * WSTRIDE + ks * 16 + kq + 8];
            asm volatile(
                "mma.sync.aligned.m16n8k16.row.col.f32.f16.f16.f32 "
                "{%0,%1,%2,%3}, {%4,%5,%6,%7}, {%8,%9}, {%0,%1,%2,%3};"
                : "+f"(d[nt][0]), "+f"(d[nt][1]), "+f"(d[nt][2]), "+f"(d[nt][3])
                : "r"(a0), "r"(a1), "r"(a2), "r"(a3), "r"(b0), "r"(b1));
        }
    }

    const int c0 = (lane & 3) * 2;
#pragma unroll
    for (int nt = 0; nt < 16; nt++) {
        int col = nt * 8 + c0;
        if (row0 < N_NODES) {
            __half2 v = __floats2half2_rn(d[nt][0] + bs[col], d[nt][1] + bs[col + 1]);
            *(__half2*)&out[(size_t)row0 * HIDDEN + col] = v;
        }
        if (row1 < N_NODES) {
            __half2 v = __floats2half2_rn(d[nt][2] + bs[col], d[nt][3] + bs[col + 1]);
            *(__half2*)&out[(size_t)row1 * HIDDEN + col] = v;
        }
    }
}

// ---------------- launch 4: exclusive scan (padded to 4) + node norm prep ----------------
__global__ __launch_bounds__(1024) void scan_prep(
    const int* __restrict__ cnt, int* __restrict__ row_ptr, int* __restrict__ cursor,
    float* __restrict__ dinv, float* __restrict__ selfw)
{
    const int PER = (N_NODES + 1023) / 1024;   // 98
    int t = threadIdx.x;
    int start = t * PER;
    int local = 0;
    for (int k = 0; k < PER; k++) {
        int i = start + k;
        if (i < N_NODES) local += (cnt[i] + 3) & ~3;   // padded
    }
    __shared__ int sh[1024];
    sh[t] = local;
    __syncthreads();
    for (int d = 1; d < 1024; d <<= 1) {
        int v = (t >= d) ? sh[t - d] : 0;
        __syncthreads();
        sh[t] += v;
        __syncthreads();
    }
    int run = sh[t] - local;
    for (int k = 0; k < PER; k++) {
        int i = start + k;
        if (i < N_NODES) {
            row_ptr[i] = run;
            cursor[i]  = run;
            run += (cnt[i] + 3) & ~3;
            float r = rsqrtf((float)cnt[i] + 1.0f);   // +1 self-loop (real degree)
            dinv[i]  = r;
            selfw[i] = (1.0f - ALPHA) * r * r;
        }
    }
    if (t == 1023) row_ptr[N_NODES] = sh[1023];
}

// ---------------- launch 5: CSR edge placement ----------------
__global__ void edge_place(const int* __restrict__ ei32, const float* __restrict__ dinv,
                           int* __restrict__ cursor, int2* __restrict__ edge)
{
    int e = blockIdx.x * 256 + threadIdx.x;
    if (e < N_EDGES) {
        int is64 = g_is64;
        int s = load_idx(ei32, e, is64);
        int d = load_idx(ei32, (long long)N_EDGES + e, is64);
        if ((unsigned)s >= N_NODES) s = 0;
        if ((unsigned)d >= N_NODES) d = 0;
        int pos = atomicAdd(&cursor[d], 1);
        float w = (1.0f - ALPHA) * dinv[s] * dinv[d];
        edge[pos] = make_int2(s, __float_as_int(w));
    }
}

// ---------------- per-hop fused pull: 16 lanes per node, fp16 in / fp32 acc ----------------
// out[n] = alpha*h0[n] + selfw[n]*cur[n] + sum_e w_e * cur[src_e]
// edge lists padded to multiple of 4 with {src=0, w=0}; no remainder loop.
template <bool FINAL>
__global__ __launch_bounds__(256) void prop_kernel(
    const __half* __restrict__ cur, const __half* __restrict__ h0,
    const float* __restrict__ selfw,
    const int* __restrict__ row_ptr, const int2* __restrict__ edge,
    void* __restrict__ outp)
{
    int gtid = blockIdx.x * 256 + threadIdx.x;
    int n = gtid >> 4;          // half-warp per node
    int l = gtid & 15;          // lane16: 8 halfs each
    if (n >= N_NODES) return;

    const size_t off = (size_t)n * HIDDEN + l * 8;
    float4 h0L, h0H, svL, svH;
    ldh8(h0 + off, h0L, h0H);
    ldh8(cur + off, svL, svH);
    float sw = selfw[n];

    float4 aL, aH;
    aL.x = ALPHA * h0L.x + sw * svL.x;  aL.y = ALPHA * h0L.y + sw * svL.y;
    aL.z = ALPHA * h0L.z + sw * svL.z;  aL.w = ALPHA * h0L.w + sw * svL.w;
    aH.x = ALPHA * h0H.x + sw * svH.x;  aH.y = ALPHA * h0H.y + sw * svH.y;
    aH.z = ALPHA * h0H.z + sw * svH.z;  aH.w = ALPHA * h0H.w + sw * svH.w;

    int beg = __ldg(row_ptr + n);
    int end = __ldg(row_ptr + n + 1);
    for (int j = beg; j < end; j += 4) {
        int2 e0 = __ldg(edge + j);
        int2 e1 = __ldg(edge + j + 1);
        int2 e2 = __ldg(edge + j + 2);
        int2 e3 = __ldg(edge + j + 3);
        float4 v0L, v0H, v1L, v1H, v2L, v2H, v3L, v3H;
        ldh8(cur + (size_t)e0.x * HIDDEN + l * 8, v0L, v0H);
        ldh8(cur + (size_t)e1.x * HIDDEN + l * 8, v1L, v1H);
        ldh8(cur + (size_t)e2.x * HIDDEN + l * 8, v2L, v2H);
        ldh8(cur + (size_t)e3.x * HIDDEN + l * 8, v3L, v3H);
        fma8(aL, aH, __int_as_float(e0.y), v0L, v0H);
        fma8(aL, aH, __int_as_float(e1.y), v1L, v1H);
        fma8(aL, aH, __int_as_float(e2.y), v2L, v2H);
        fma8(aL, aH, __int_as_float(e3.y), v3L, v3H);
    }

    if (FINAL) {
        float* o = (float*)outp + off;
        *(float4*)o       = aL;
        *(float4*)(o + 4) = aH;
    } else {
        __half* o = (__half*)outp + off;
        sth4(o, aL);
        sth4(o + 4, aH);
    }
}

// ---------------- launch ----------------
extern "C" void kernel_launch(void* const* d_in, const int* in_sizes, int n_in,
                              void* d_out, int out_size)
{
    const float* x    = (const float*)d_in[0];
    const int*   ei32 = (const int*)d_in[1];    // int32 OR int64 (device probe)
    const float* W    = (const float*)d_in[2];
    const float* b    = (const float*)d_in[3];
    float* out = (float*)d_out;

    __half *xh, *Wh, *h0h, *bufA, *bufB;
    float *dinv, *selfw;
    int *cnt, *row_ptr, *cursor;
    int2 *edge;
    cudaGetSymbolAddress((void**)&xh,      g_xh);
    cudaGetSymbolAddress((void**)&Wh,      g_Wh);
    cudaGetSymbolAddress((void**)&h0h,     g_h0h);
    cudaGetSymbolAddress((void**)&bufA,    g_bufA);
    cudaGetSymbolAddress((void**)&bufB,    g_bufB);
    cudaGetSymbolAddress((void**)&cnt,     g_cnt);
    cudaGetSymbolAddress((void**)&row_ptr, g_rowptr);
    cudaGetSymbolAddress((void**)&cursor,  g_cursor);
    cudaGetSymbolAddress((void**)&dinv,    g_dinv);
    cudaGetSymbolAddress((void**)&selfw,   g_selfw);
    cudaGetSymbolAddress((void**)&edge,    g_edge);

    const int NB_N = (N_NODES + 255) / 256;            // 391
    const int NB_E = (N_EDGES + 255) / 256;            // 2344
    const int NB_C = (N_NODES * HIDDEN / 4 + 255) / 256; // 12500
    const int NB_G = (N_NODES + 127) / 128;            // 782

    probe_zero    <<<NB_N, 256>>>(ei32, cnt, edge);               // 0
    convert_kernel<<<NB_C, 256>>>(x, W, xh, Wh);                  // 1
    deg_count     <<<NB_E, 256>>>(ei32, cnt);                     // 2
    gemm_hmma     <<<NB_G, 256>>>(xh, Wh, b, h0h);                // 3 (profiled)
    scan_prep     <<<1, 1024>>>(cnt, row_ptr, cursor, dinv, selfw); // 4
    edge_place    <<<NB_E, 256>>>(ei32, dinv, cursor, edge);      // 5

    const int NB_PROP = (N_NODES * 16 + 255) / 256;    // 6250
    const __half* cur = h0h;
    for (int hop = 0; hop < KHOPS; hop++) {
        if (hop == KHOPS - 1) {
            prop_kernel<true><<<NB_PROP, 256>>>(cur, h0h, selfw, row_ptr, edge, out);
        } else {
            __half* nxt = (hop & 1) ? bufB : bufA;
            prop_kernel<false><<<NB_PROP, 256>>>(cur, h0h, selfw, row_ptr, edge, nxt);
            cur = nxt;
        }
    }
}